// round 12
// baseline (speedup 1.0000x reference)
#include <cuda_runtime.h>
#include <math.h>

// Problem shape (fixed by setup_inputs)
#define BB 8
#define CC 256
#define NN 2048
#define KK 24
#define ROWS (BB * CC * NN)        // 4,194,304
#define BLOCK 256
#define RPB 256                    // rows per block in k_reduce
#define F4PB (RPB * KK / 4)        // 1536 float4s per block
#define NBLK (ROWS / RPB)          // 16,384 blocks; 8 per (b,c) slice
#define BN_EPS 1e-5f
#define INV_BN_COUNT (1.0f / (float)(BB * NN))   // 1/16384

// Deterministic scratch (static __device__ globals — no runtime allocation)
__device__ float g_psum[NBLK];     // per-block sum of m
__device__ float g_psq[NBLK];      // per-block sum of m^2
__device__ float g_scale[CC];      // invstd * gamma
__device__ float g_shift[CC];      // beta - mean * invstd * gamma

// ---------------------------------------------------------------------------
// Kernel 1: per-row mean over K (x2) with perfectly coalesced, evict-first
// (__ldcs) loads. Each block owns 256 consecutive rows = 1536 float4, loaded
// as 6 contiguous 4 KB sweeps. Per-float4 partials staged in smem; thread t
// folds the 6 partials of row t. The x stream is single-use: .cs keeps the
// freshly written m[] resident in L2 for the epilogue kernels.
// Note: up/down in the reference cancels exactly (e_x is a per-row scalar and
// down == e_x), so _k_anp(x) + mean_K(x) == 2 * mean_K(x).
// ---------------------------------------------------------------------------
__global__ __launch_bounds__(BLOCK) void k_reduce(const float* __restrict__ x,
                                                  float* __restrict__ m_out) {
    __shared__ float ps[F4PB];                  // 6 KB partial sums
    const float4* __restrict__ p =
        reinterpret_cast<const float4*>(x) + (size_t)blockIdx.x * F4PB;
    const int t = threadIdx.x;

    #pragma unroll
    for (int j = 0; j < 6; j++) {
        const float4 v = __ldcs(p + t + BLOCK * j);   // coalesced, evict-first
        ps[t + BLOCK * j] = (v.x + v.y) + (v.z + v.w);
    }
    __syncthreads();

    // Row t's 24 elements are flat float4s [6t, 6t+6).
    const int b6 = 6 * t;
    const float s = ((ps[b6] + ps[b6 + 1]) + (ps[b6 + 2] + ps[b6 + 3]))
                  + (ps[b6 + 4] + ps[b6 + 5]);
    const float m = s * (2.0f / (float)KK);
    m_out[blockIdx.x * RPB + t] = m;

    // Deterministic block reduction of (m, m^2): warp shuffle + smem.
    float sm = m;
    float sq = m * m;
    #pragma unroll
    for (int off = 16; off > 0; off >>= 1) {
        sm += __shfl_down_sync(0xFFFFFFFFu, sm, off);
        sq += __shfl_down_sync(0xFFFFFFFFu, sq, off);
    }
    __shared__ float sh_m[BLOCK / 32];
    __shared__ float sh_q[BLOCK / 32];
    const int lane = t & 31;
    const int wid  = t >> 5;
    if (lane == 0) { sh_m[wid] = sm; sh_q[wid] = sq; }
    __syncthreads();
    if (wid == 0) {
        float tm = (lane < BLOCK / 32) ? sh_m[lane] : 0.0f;
        float tq = (lane < BLOCK / 32) ? sh_q[lane] : 0.0f;
        #pragma unroll
        for (int off = 4; off > 0; off >>= 1) {
            tm += __shfl_down_sync(0xFFFFFFFFu, tm, off);
            tq += __shfl_down_sync(0xFFFFFFFFu, tq, off);
        }
        if (lane == 0) {
            g_psum[blockIdx.x] = tm;
            g_psq[blockIdx.x]  = tq;
        }
    }
}

// ---------------------------------------------------------------------------
// Kernel 2: parallel per-channel stats fold -> fused scale/shift.
// 256 blocks (one per channel c = blockIdx.x) x 64 threads. Thread t = b*8+j
// loads partial ((b*CC+c)*8+j); two-warp shuffle fold + smem combine, fixed
// order -> deterministic. ~1 us total; replaces the per-block redundant fold
// that was capping k_bn_gelu's issue rate at 49.8%.
// ---------------------------------------------------------------------------
__global__ __launch_bounds__(64) void k_scale(const float* __restrict__ gamma,
                                              const float* __restrict__ beta) {
    const int c = blockIdx.x;
    const int t = threadIdx.x;                 // 0..63 = b*8 + j
    const int b = t >> 3, j = t & 7;
    const int idx = (b * CC + c) * 8 + j;

    float sm = g_psum[idx];
    float sq = g_psq[idx];
    #pragma unroll
    for (int off = 16; off > 0; off >>= 1) {
        sm += __shfl_down_sync(0xFFFFFFFFu, sm, off);
        sq += __shfl_down_sync(0xFFFFFFFFu, sq, off);
    }
    __shared__ float sh_m[2], sh_q[2];
    if ((t & 31) == 0) { sh_m[t >> 5] = sm; sh_q[t >> 5] = sq; }
    __syncthreads();
    if (t == 0) {
        const float tsm = sh_m[0] + sh_m[1];
        const float tsq = sh_q[0] + sh_q[1];
        const float mean  = tsm * INV_BN_COUNT;
        const float var   = tsq * INV_BN_COUNT - mean * mean;  // biased (torch BN)
        const float scale = rsqrtf(var + BN_EPS) * gamma[c];
        g_scale[c] = scale;
        g_shift[c] = beta[c] - mean * scale;
    }
}

// ---------------------------------------------------------------------------
// Kernel 3: pure elementwise BN affine + exact GELU, in place, float4.
// c is warp-uniform (32 aligned float4s never cross the 512-float4 channel
// boundary), so the scale/shift loads broadcast. No smem, no syncs.
// ---------------------------------------------------------------------------
__device__ __forceinline__ float gelu_exact(float y) {
    return 0.5f * y * (1.0f + erff(y * 0.70710678118654752f));
}

__global__ __launch_bounds__(BLOCK) void k_bn_gelu(float* __restrict__ m_io) {
    const int i4 = blockIdx.x * BLOCK + threadIdx.x;   // float4 index
    const int c  = (i4 >> 9) & (CC - 1);               // (i4*4 / NN) % CC
    const float scale = g_scale[c];
    const float shift = g_shift[c];

    float4 v = reinterpret_cast<const float4*>(m_io)[i4];
    v.x = gelu_exact(fmaf(v.x, scale, shift));
    v.y = gelu_exact(fmaf(v.y, scale, shift));
    v.z = gelu_exact(fmaf(v.z, scale, shift));
    v.w = gelu_exact(fmaf(v.w, scale, shift));
    reinterpret_cast<float4*>(m_io)[i4] = v;
}

// ---------------------------------------------------------------------------
extern "C" void kernel_launch(void* const* d_in, const int* in_sizes, int n_in,
                              void* d_out, int out_size) {
    const float* x     = (const float*)d_in[0];   // [B, C, N, K] f32
    const float* gamma = (const float*)d_in[1];   // [C]
    const float* beta  = (const float*)d_in[2];   // [C]
    float* out = (float*)d_out;                   // [B, C, N] f32

    k_reduce<<<NBLK, BLOCK>>>(x, out);
    k_scale<<<CC, 64>>>(gamma, beta);
    k_bn_gelu<<<ROWS / 4 / BLOCK, BLOCK>>>(out);
}

// round 15
// speedup vs baseline: 1.0275x; 1.0275x over previous
#include <cuda_runtime.h>
#include <math.h>

// Problem shape (fixed by setup_inputs)
#define BB 8
#define CC 256
#define NN 2048
#define KK 24
#define ROWS (BB * CC * NN)        // 4,194,304
#define BLOCK 256
#define RPB 256                    // rows per block in k_reduce
#define F4PB (RPB * KK / 4)        // 1536 float4s per block
#define NBLK (ROWS / RPB)          // 16,384 blocks; 8 per (b,c) slice
#define BN_EPS 1e-5f
#define INV_BN_COUNT (1.0f / (float)(BB * NN))   // 1/16384

// Deterministic scratch (static __device__ globals — no runtime allocation)
__device__ float g_psum[NBLK];     // per-block sum of m
__device__ float g_psq[NBLK];      // per-block sum of m^2
__device__ float g_scale[CC];      // invstd * gamma
__device__ float g_shift[CC];      // beta - mean * invstd * gamma

// ---------------------------------------------------------------------------
// Kernel 1 (UNCHANGED — measured at 83.2% of HBM spec; at the streaming
// ceiling): per-row mean over K (x2) with coalesced, evict-first loads.
// Note: up/down in the reference cancels exactly (e_x is a per-row scalar and
// down == e_x), so _k_anp(x) + mean_K(x) == 2 * mean_K(x).
// ---------------------------------------------------------------------------
__global__ __launch_bounds__(BLOCK) void k_reduce(const float* __restrict__ x,
                                                  float* __restrict__ m_out) {
    __shared__ float ps[F4PB];                  // 6 KB partial sums
    const float4* __restrict__ p =
        reinterpret_cast<const float4*>(x) + (size_t)blockIdx.x * F4PB;
    const int t = threadIdx.x;

    #pragma unroll
    for (int j = 0; j < 6; j++) {
        const float4 v = __ldcs(p + t + BLOCK * j);   // coalesced, evict-first
        ps[t + BLOCK * j] = (v.x + v.y) + (v.z + v.w);
    }
    __syncthreads();

    // Row t's 24 elements are flat float4s [6t, 6t+6).
    const int b6 = 6 * t;
    const float s = ((ps[b6] + ps[b6 + 1]) + (ps[b6 + 2] + ps[b6 + 3]))
                  + (ps[b6 + 4] + ps[b6 + 5]);
    const float m = s * (2.0f / (float)KK);
    m_out[blockIdx.x * RPB + t] = m;

    // Deterministic block reduction of (m, m^2): warp shuffle + smem.
    float sm = m;
    float sq = m * m;
    #pragma unroll
    for (int off = 16; off > 0; off >>= 1) {
        sm += __shfl_down_sync(0xFFFFFFFFu, sm, off);
        sq += __shfl_down_sync(0xFFFFFFFFu, sq, off);
    }
    __shared__ float sh_m[BLOCK / 32];
    __shared__ float sh_q[BLOCK / 32];
    const int lane = t & 31;
    const int wid  = t >> 5;
    if (lane == 0) { sh_m[wid] = sm; sh_q[wid] = sq; }
    __syncthreads();
    if (wid == 0) {
        float tm = (lane < BLOCK / 32) ? sh_m[lane] : 0.0f;
        float tq = (lane < BLOCK / 32) ? sh_q[lane] : 0.0f;
        #pragma unroll
        for (int off = 4; off > 0; off >>= 1) {
            tm += __shfl_down_sync(0xFFFFFFFFu, tm, off);
            tq += __shfl_down_sync(0xFFFFFFFFu, tq, off);
        }
        if (lane == 0) {
            g_psum[blockIdx.x] = tm;
            g_psq[blockIdx.x]  = tq;
        }
    }
}

// ---------------------------------------------------------------------------
// Kernel 2: parallel per-channel stats fold -> fused scale/shift.
// 128 blocks x 128 threads; each block handles 2 channels (one per warp pair).
// Warp pair w owns channel c = blockIdx.x*2 + w; thread tp=b*8+j within the
// pair loads partial ((b*CC+c)*8+j); fixed-order fold -> deterministic.
// ---------------------------------------------------------------------------
__global__ __launch_bounds__(128) void k_scale(const float* __restrict__ gamma,
                                               const float* __restrict__ beta) {
    const int t  = threadIdx.x;
    const int w  = t >> 6;                     // which channel half (0/1)
    const int tp = t & 63;                     // 0..63 = b*8 + j
    const int c  = blockIdx.x * 2 + w;
    const int b = tp >> 3, j = tp & 7;
    const int idx = (b * CC + c) * 8 + j;

    float sm = g_psum[idx];
    float sq = g_psq[idx];
    #pragma unroll
    for (int off = 16; off > 0; off >>= 1) {
        sm += __shfl_down_sync(0xFFFFFFFFu, sm, off);
        sq += __shfl_down_sync(0xFFFFFFFFu, sq, off);
    }
    __shared__ float sh_m[4], sh_q[4];
    if ((t & 31) == 0) { sh_m[t >> 5] = sm; sh_q[t >> 5] = sq; }
    __syncthreads();
    if (tp == 0) {
        const float tsm = sh_m[2 * w] + sh_m[2 * w + 1];
        const float tsq = sh_q[2 * w] + sh_q[2 * w + 1];
        const float mean  = tsm * INV_BN_COUNT;
        const float var   = tsq * INV_BN_COUNT - mean * mean;  // biased (torch BN)
        const float scale = rsqrtf(var + BN_EPS) * gamma[c];
        g_scale[c] = scale;
        g_shift[c] = beta[c] - mean * scale;
    }
}

// ---------------------------------------------------------------------------
// Kernel 3: pure elementwise BN affine + exact GELU, in place.
// 2 float4 per thread, both loads issued up-front (MLP 2 covers the L2-hit
// latency on the L2-resident m). Both halves of a block lie in the same
// 512-float4 channel row, so scale/shift loads broadcast.
// ---------------------------------------------------------------------------
__device__ __forceinline__ float gelu_exact(float y) {
    return 0.5f * y * (1.0f + erff(y * 0.70710678118654752f));
}

__global__ __launch_bounds__(BLOCK) void k_bn_gelu(float* __restrict__ m_io) {
    const int base = blockIdx.x * (BLOCK * 2) + threadIdx.x;   // float4 index
    const int iA = base;
    const int iB = base + BLOCK;
    float4* __restrict__ p4 = reinterpret_cast<float4*>(m_io);

    // Issue both loads before any dependent math.
    float4 a = p4[iA];
    float4 b = p4[iB];

    const int cA = (iA >> 9) & (CC - 1);
    const int cB = (iB >> 9) & (CC - 1);
    const float sA = g_scale[cA], hA = g_shift[cA];
    const float sB = g_scale[cB], hB = g_shift[cB];

    a.x = gelu_exact(fmaf(a.x, sA, hA));
    a.y = gelu_exact(fmaf(a.y, sA, hA));
    a.z = gelu_exact(fmaf(a.z, sA, hA));
    a.w = gelu_exact(fmaf(a.w, sA, hA));
    b.x = gelu_exact(fmaf(b.x, sB, hB));
    b.y = gelu_exact(fmaf(b.y, sB, hB));
    b.z = gelu_exact(fmaf(b.z, sB, hB));
    b.w = gelu_exact(fmaf(b.w, sB, hB));

    p4[iA] = a;
    p4[iB] = b;
}

// ---------------------------------------------------------------------------
extern "C" void kernel_launch(void* const* d_in, const int* in_sizes, int n_in,
                              void* d_out, int out_size) {
    const float* x     = (const float*)d_in[0];   // [B, C, N, K] f32
    const float* gamma = (const float*)d_in[1];   // [C]
    const float* beta  = (const float*)d_in[2];   // [C]
    float* out = (float*)d_out;                   // [B, C, N] f32

    k_reduce<<<NBLK, BLOCK>>>(x, out);
    k_scale<<<CC / 2, 128>>>(gamma, beta);
    k_bn_gelu<<<ROWS / 4 / (BLOCK * 2), BLOCK>>>(out);
}